// round 5
// baseline (speedup 1.0000x reference)
#include <cuda_runtime.h>
#include <math.h>
#include <cstdint>

// Hausdorff, D=H=W=20, V=8000, batch 2. Exact integer squared-EDT.
// 16 CTAs = 4 clusters of 4 (cluster = one transform t = n*2+m, CTA = 5 x-slabs).
// F2 lives in SMEM; x-pass reads it cross-CTA via DSMEM. Sync = barrier.cluster.
// Tail: 4 cluster leaders -> tiny global combine; last leader finalizes + resets.

#define INF_S 32000   // squared-distance "infinity" (max legit = 3*19^2 = 1083)

__device__ volatile unsigned g_res[4];   // per-transform max d2 + 1 (0 = none); zero-init
__device__ volatile unsigned g_any[2];   // any(mask A) per sample; zero-init
__device__ unsigned g_done = 0;

__global__ void __launch_bounds__(1024, 1) __cluster_dims__(4, 1, 1)
haus_cluster(const float* __restrict__ predict,
             const float* __restrict__ targetp,
             float* __restrict__ out)
{
    __shared__ unsigned char mS[2000];
    __shared__ short F1[2000];
    __shared__ short F2[2000];
    __shared__ int sred, ssany;
    __shared__ unsigned comb[2];     // combine slots (used on rank 0): [0]=max enc, [1]=anyS

    const int cta  = blockIdx.x;
    const int t    = cta >> 2;       // transform 0..3
    const int rank = cta & 3;        // cluster rank 0..3
    const int n = t >> 1, m = t & 1;
    const int tid = threadIdx.x;

    const float* setSrc = (m ? targetp : predict) + n * 8000 + rank * 2000;
    const float* othSrc = (m ? predict : targetp) + n * 8000 + rank * 2000;

    if (tid == 0) { sred = 0; ssany = 0; comb[0] = 0; comb[1] = 0; }

    // ---- masks (jnp.round == round-half-even == rintf); 2 cells per thread ----
    int oo0 = 0, oo1 = 0, sAny = 0;
    if (tid < 1000) {
        float s0 = setSrc[tid],        o0 = othSrc[tid];
        float s1 = setSrc[tid + 1000], o1 = othSrc[tid + 1000];
        int b0 = (rintf(s0) != 0.0f), c0 = (rintf(o0) != 0.0f);
        int b1 = (rintf(s1) != 0.0f), c1 = (rintf(o1) != 0.0f);
        mS[tid]        = (unsigned char)b0;
        mS[tid + 1000] = (unsigned char)b1;
        oo0 = c0 & (b0 ^ 1);           // "other-only" flags
        oo1 = c1 & (b1 ^ 1);
        sAny = b0 | b1;
    }
    __syncthreads();

    // ---- z-pass ----
    if (tid < 1000) {
        #pragma unroll
        for (int h = 0; h < 2; h++) {
            int v = tid + h * 1000;
            int z = v % 20, base = v - z;
            int best = INF_S;
            #pragma unroll
            for (int zp = 0; zp < 20; zp++) {
                int dz = z - zp;
                best = min(best, mS[base + zp] ? dz * dz : INF_S);
            }
            F1[v] = (short)best;
        }
    }
    __syncthreads();

    // ---- y-pass ----
    if (tid < 1000) {
        #pragma unroll
        for (int h = 0; h < 2; h++) {
            int v = tid + h * 1000;
            int y = (v / 20) % 20;
            int colbase = v - y * 20;      // xloc*400 + z
            int best = INF_S;
            #pragma unroll
            for (int yp = 0; yp < 20; yp++) {
                int dy = y - yp;
                best = min(best, (int)F1[colbase + yp * 20] + dy * dy);
            }
            F2[v] = (short)min(best, INF_S);
        }
    }

    // ---- cluster barrier #1 (release F2 cluster-wide) ----
    asm volatile("barrier.cluster.arrive.aligned;" ::: "memory");
    asm volatile("barrier.cluster.wait.aligned;"   ::: "memory");

    // DSMEM base of F2 in every cluster rank
    uint32_t f2base;
    asm("{ .reg .u64 tt; cvta.to.shared.u64 tt, %1; cvt.u32.u64 %0, tt; }"
        : "=r"(f2base) : "l"(F2));
    uint32_t bmap[4];
    #pragma unroll
    for (int r = 0; r < 4; r++)
        asm("mapa.shared::cluster.u32 %0, %1, %2;" : "=r"(bmap[r]) : "r"(f2base), "r"(r));

    // ---- x-pass + classification ----
    int localEnc = 0;                    // encoded best+1; 0 = none
    if (tid < 1000) {
        #pragma unroll
        for (int h = 0; h < 2; h++) {
            int v  = tid + h * 1000;
            int yz = v % 400;
            int x  = rank * 5 + v / 400;
            int best = 1 << 29;
            #pragma unroll
            for (int xp = 0; xp < 20; xp++) {
                uint32_t addr = bmap[xp / 5] + (uint32_t)(((xp % 5) * 400 + yz) * 2);
                unsigned short fv;
                asm volatile("ld.shared::cluster.u16 %0, [%1];" : "=h"(fv) : "r"(addr));
                int dx = x - xp;
                best = min(best, (int)fv + dx * dx);
            }
            int oo = h ? oo1 : oo0;
            if (oo) localEnc = max(localEnc, best + 1);
        }
    }
    localEnc = __reduce_max_sync(0xffffffffu, localEnc);
    int anyW = __any_sync(0xffffffffu, sAny);
    if ((tid & 31) == 0) {
        if (localEnc) atomicMax(&sred, localEnc);
        if (anyW) ssany = 1;             // benign race: all writers store 1
    }
    __syncthreads();

    // ---- push CTA result to cluster rank 0 via DSMEM red ----
    if (tid == 0) {
        uint32_t cbase;
        asm("{ .reg .u64 tt; cvta.to.shared.u64 tt, %1; cvt.u32.u64 %0, tt; }"
            : "=r"(cbase) : "l"(comb));
        uint32_t c0;
        asm("mapa.shared::cluster.u32 %0, %1, %2;" : "=r"(c0) : "r"(cbase), "r"(0));
        unsigned e = (unsigned)sred;
        if (e)
            asm volatile("red.shared::cluster.max.u32 [%0], %1;" :: "r"(c0), "r"(e) : "memory");
        if (m == 0 && ssany)
            asm volatile("red.shared::cluster.or.b32 [%0], %1;" :: "r"(c0 + 4), "r"(1u) : "memory");
    }

    // ---- cluster barrier #2 (release the reds into rank 0's smem) ----
    asm volatile("barrier.cluster.arrive.aligned;" ::: "memory");
    asm volatile("barrier.cluster.wait.aligned;"   ::: "memory");

    // ---- tiny global tail: 4 cluster leaders only ----
    if (rank == 0 && tid == 0) {
        unsigned enc = comb[0], anyv = comb[1];
        g_res[t] = enc;                          // single writer per t
        if (m == 0 && anyv) g_any[n] = 1;
        __threadfence();
        unsigned old = atomicAdd(&g_done, 1);
        if (old == 3) {
            __threadfence();
            float sum = 0.0f;
            #pragma unroll
            for (int nn = 0; nn < 2; nn++) {
                int a2 = (int)g_res[nn * 2 + 1] - 1;   // distA (transform m==1)
                int b2 = (int)g_res[nn * 2 + 0] - 1;   // distB (transform m==0)
                int aA = (int)g_any[nn];
                float dA = 0.0f;
                if (a2 >= 0) dA = (a2 > 1083) ? 1e9f : sqrtf((float)a2) * 0.05f;
                float dB = 0.0f;
                if (b2 >= 0) dB = aA ? ((b2 > 1083) ? 1e9f : sqrtf((float)b2) * 0.05f)
                                     : 999.0f;
                sum += fmaxf(dA, dB);
                g_res[nn * 2 + 0] = 0; g_res[nn * 2 + 1] = 0; g_any[nn] = 0;
            }
            out[0] = sum * 0.5f;
            atomicExch(&g_done, 0);              // restore static-init state for replay
        }
    }
}

extern "C" void kernel_launch(void* const* d_in, const int* in_sizes, int n_in,
                              void* d_out, int out_size)
{
    const float* predict = (const float*)d_in[0];
    const float* targetp = (const float*)d_in[1];
    haus_cluster<<<16, 1024>>>(predict, targetp, (float*)d_out);
}

// round 6
// speedup vs baseline: 1.3761x; 1.3761x over previous
#include <cuda_runtime.h>
#include <math.h>

// Hausdorff, D=H=W=20, V=8000, batch 2. Exact integer squared-EDT.
// Two kernels with Programmatic Dependent Launch:
//   k1 (80 blocks = 4 transforms x 20 x-slabs): masks, O(1) bit-trick z-pass,
//      y-pass in SMEM -> g_F2, other-only flags, anyA.
//   k2 (80 blocks, PDL): overlapped launch; gridDependencySynchronize, then
//      x-pass from L2, block max-reduce, done-counter tail finalizes + resets.

#define INF_S 32000   // squared-distance "infinity" (max legit = 3*19^2 = 1083)
#define PAD   8

__device__ int           g_F2[4][8000];     // after z+y passes, t = n*2+m
__device__ unsigned char g_oo[4][8000];     // "other-only" flag per cell
__device__ unsigned      g_gmax[4 * PAD];   // per-transform max d2 + 1 (0 = none)
__device__ unsigned      g_any[2 * PAD];    // any(mask A) per sample
__device__ unsigned      g_done = 0;

__global__ void __launch_bounds__(416, 1)
k1_zy(const float* __restrict__ predict, const float* __restrict__ targetp)
{
    // allow the dependent k2 to start launching immediately
    cudaTriggerProgrammaticLaunchCompletion();

    __shared__ unsigned rowbits[20];   // z-occupancy bits per y row
    __shared__ short F1[400];

    const int b = blockIdx.x;          // t*20 + x
    const int t = b / 20, x = b - t * 20;
    const int n = t >> 1, m = t & 1;
    const float* setSrc = (m ? targetp : predict) + n * 8000 + x * 400;
    const float* othSrc = (m ? predict : targetp) + n * 8000 + x * 400;
    const int tid = threadIdx.x;

    if (tid < 20) rowbits[tid] = 0;
    __syncthreads();

    int y = 0, z = 0, s = 0;
    if (tid < 400) {
        y = tid / 20; z = tid - y * 20;
        s     = (rintf(setSrc[tid]) != 0.0f);     // jnp.round == rintf (half-even)
        int o = (rintf(othSrc[tid]) != 0.0f);
        g_oo[t][x * 400 + tid] = (unsigned char)(o & (s ^ 1));
        if (s) atomicOr(&rowbits[y], 1u << z);
    }
    // anyA: only transforms with set == A (m == 0)
    int anyv = __any_sync(0xffffffffu, s);
    if (m == 0 && (tid & 31) == 0 && anyv) atomicOr(&g_any[n * PAD], 1u);
    __syncthreads();

    // z-pass: O(1) nearest set bit
    if (tid < 400) {
        unsigned mask = rowbits[y];
        int dist = 100;                           // >19 == none in this row
        unsigned lo = mask & ((2u << z) - 1u);
        if (lo) dist = z - (31 - __clz(lo));
        unsigned hi = mask >> z;
        if (hi) dist = min(dist, __ffs(hi) - 1);
        F1[tid] = (short)((dist <= 19) ? dist * dist : INF_S);
    }
    __syncthreads();

    // y-pass
    if (tid < 400) {
        int best = INF_S;
        #pragma unroll
        for (int yp = 0; yp < 20; yp++) {
            int dy = y - yp;
            best = min(best, (int)F1[yp * 20 + z] + dy * dy);
        }
        g_F2[t][x * 400 + tid] = min(best, INF_S);
    }
}

__global__ void __launch_bounds__(416, 1)
k2_x(float* __restrict__ out)
{
    // wait until k1 has fully completed (writes visible)
    cudaGridDependencySynchronize();

    __shared__ int sred;
    const int b = blockIdx.x;
    const int t = b / 20, x = b - t * 20;
    const int tid = threadIdx.x;
    if (tid == 0) sred = 0;
    __syncthreads();

    int enc = 0;                                  // best+1 encoded; 0 = none
    if (tid < 400) {
        const int* __restrict__ f2 = g_F2[t] + tid;   // yz = tid
        int best = 1 << 29;
        #pragma unroll
        for (int xp = 0; xp < 20; xp++) {
            int dx = x - xp;
            best = min(best, __ldcg(f2 + xp * 400) + dx * dx);
        }
        if (g_oo[t][x * 400 + tid]) enc = best + 1;
    }
    enc = __reduce_max_sync(0xffffffffu, enc);
    if ((tid & 31) == 0 && enc) atomicMax(&sred, enc);
    __syncthreads();

    if (tid == 0) {
        if (sred) atomicMax(&g_gmax[t * PAD], (unsigned)sred);
        __threadfence();
        unsigned done = atomicAdd(&g_done, 1);
        if (done == 79) {
            __threadfence();
            volatile unsigned* vmax = (volatile unsigned*)g_gmax;
            volatile unsigned* vany = (volatile unsigned*)g_any;
            float sum = 0.0f;
            #pragma unroll
            for (int nn = 0; nn < 2; nn++) {
                int a2   = (int)vmax[(nn * 2 + 1) * PAD] - 1;   // A-only -> B (set=B, m=1)
                int b2   = (int)vmax[(nn * 2 + 0) * PAD] - 1;   // B-only -> A (set=A, m=0)
                int anyA = (int)vany[nn * PAD];
                float dA = 0.0f;
                if (a2 >= 0) dA = (a2 > 1083) ? 1e9f : sqrtf((float)a2) * 0.05f;
                float dB = 0.0f;
                if (b2 >= 0) dB = anyA ? ((b2 > 1083) ? 1e9f : sqrtf((float)b2) * 0.05f)
                                       : 999.0f;
                sum += fmaxf(dA, dB);
                vmax[(nn * 2 + 0) * PAD] = 0;
                vmax[(nn * 2 + 1) * PAD] = 0;
                vany[nn * PAD] = 0;
            }
            out[0] = sum * 0.5f;
            atomicExch(&g_done, 0);               // restore for next graph replay
        }
    }
}

extern "C" void kernel_launch(void* const* d_in, const int* in_sizes, int n_in,
                              void* d_out, int out_size)
{
    const float* predict = (const float*)d_in[0];
    const float* targetp = (const float*)d_in[1];

    k1_zy<<<80, 416>>>(predict, targetp);

    cudaLaunchConfig_t cfg = {};
    cfg.gridDim  = dim3(80);
    cfg.blockDim = dim3(416);
    cfg.dynamicSmemBytes = 0;
    cfg.stream = 0;
    cudaLaunchAttribute attr[1];
    attr[0].id = cudaLaunchAttributeProgrammaticStreamSerialization;
    attr[0].val.programmaticStreamSerializationAllowed = 1;
    cfg.attrs = attr;
    cfg.numAttrs = 1;
    cudaLaunchKernelEx(&cfg, k2_x, (float*)d_out);
}

// round 7
// speedup vs baseline: 1.7353x; 1.2610x over previous
#include <cuda_runtime.h>
#include <math.h>

// Hausdorff, D=H=W=20, V=8000, batch 2. Exact integer squared-EDT.
// ONE kernel, NO cross-block dependency: block = (transform t, z-plane z0).
// Each thread (x,y) builds the 20-bit z-occupancy of its own row from gmem,
// does the z-pass in O(1) (clz/ffs), then y- and x-passes entirely in SMEM
// for the fixed z0 plane. Tail: per-block atomicMax + 80-way done counter;
// last block finalizes and resets globals (graph-replay safe).

#define INF_S 32000   // squared-distance "infinity" (max legit = 3*19^2 = 1083)
#define PAD   8

__device__ unsigned g_gmax[4 * PAD];   // per-transform max d2+1 (0 = none); zero-init
__device__ unsigned g_any[2 * PAD];    // any(mask A) per sample; zero-init
__device__ unsigned g_done = 0;

__global__ void __launch_bounds__(416, 1)
haus_plane(const float* __restrict__ predict,
           const float* __restrict__ targetp,
           float* __restrict__ out)
{
    __shared__ int F1[400];   // z-pass result for plane z0, index x*20+y
    __shared__ int F2[400];   // y-pass result, index x*20+y
    __shared__ int sred;
    __shared__ int sany;

    const int b  = blockIdx.x;       // t*20 + z0
    const int t  = b / 20, z0 = b - t * 20;
    const int n  = t >> 1,  m  = t & 1;
    const float* setSrc = (m ? targetp : predict) + n * 8000;
    const float* othSrc = (m ? predict : targetp) + n * 8000;
    const int tid = threadIdx.x;

    if (tid == 0) { sred = 0; sany = 0; }

    int x = 0, y = 0, oo = 0;
    unsigned rowbits = 0;
    if (tid < 400) {
        x = tid / 20; y = tid - x * 20;
        // Load own (x,y) row over z: 20 contiguous floats = 5 x float4.
        const float4* rp = (const float4*)(setSrc + tid * 20);
        #pragma unroll
        for (int q = 0; q < 5; q++) {
            float4 v = rp[q];
            // jnp.round == round-half-even == rintf
            rowbits |= (rintf(v.x) != 0.0f ? 1u : 0u) << (q * 4 + 0);
            rowbits |= (rintf(v.y) != 0.0f ? 1u : 0u) << (q * 4 + 1);
            rowbits |= (rintf(v.z) != 0.0f ? 1u : 0u) << (q * 4 + 2);
            rowbits |= (rintf(v.w) != 0.0f ? 1u : 0u) << (q * 4 + 3);
        }
        // z-pass at fixed z0: nearest set bit in own row, O(1).
        int dist = 100;
        unsigned lo = rowbits & ((2u << z0) - 1u);
        if (lo) dist = z0 - (31 - __clz(lo));
        unsigned hi = rowbits >> z0;
        if (hi) dist = min(dist, __ffs(hi) - 1);
        F1[tid] = (dist <= 19) ? dist * dist : INF_S;

        // own-cell flags
        int s = (rowbits >> z0) & 1;
        int o = (rintf(othSrc[tid * 20 + z0]) != 0.0f);
        oo = o & (s ^ 1);                  // "other-only" point
    }
    // anyA = any set bit anywhere (rowbits covers the full volume across the block)
    int anyW = __any_sync(0xffffffffu, rowbits != 0);
    if ((tid & 31) == 0 && anyW) sany = 1;     // benign race
    __syncthreads();

    // ---- y-pass (all in SMEM): F2(x,y) = min_yp F1(x,yp) + (y-yp)^2 ----
    if (tid < 400) {
        int c[20];
        int base = x * 20;
        #pragma unroll
        for (int yp = 0; yp < 20; yp++) {
            int dy = y - yp;
            c[yp] = F1[base + yp] + dy * dy;
        }
        #pragma unroll
        for (int st = 1; st < 20; st <<= 1)
            #pragma unroll
            for (int i = 0; i + st < 20; i += (st << 1)) c[i] = min(c[i], c[i + st]);
        F2[tid] = min(c[0], INF_S);
    }
    __syncthreads();

    // ---- x-pass + classification ----
    int enc = 0;                                  // best+1 encoded; 0 = none
    if (tid < 400) {
        int c[20];
        #pragma unroll
        for (int xp = 0; xp < 20; xp++) {
            int dx = x - xp;
            c[xp] = F2[xp * 20 + y] + dx * dx;
        }
        #pragma unroll
        for (int st = 1; st < 20; st <<= 1)
            #pragma unroll
            for (int i = 0; i + st < 20; i += (st << 1)) c[i] = min(c[i], c[i + st]);
        if (oo) enc = c[0] + 1;
    }
    enc = __reduce_max_sync(0xffffffffu, enc);
    if ((tid & 31) == 0 && enc) atomicMax(&sred, enc);
    __syncthreads();

    // ---- tail: one global atomicMax per block; last block finalizes ----
    if (tid == 0) {
        if (sred) atomicMax(&g_gmax[t * PAD], (unsigned)sred);
        if (m == 0 && sany) atomicOr(&g_any[n * PAD], 1u);
        __threadfence();
        unsigned done = atomicAdd(&g_done, 1);
        if (done == 79) {
            __threadfence();
            volatile unsigned* vmax = (volatile unsigned*)g_gmax;
            volatile unsigned* vany = (volatile unsigned*)g_any;
            float sum = 0.0f;
            #pragma unroll
            for (int nn = 0; nn < 2; nn++) {
                int a2   = (int)vmax[(nn * 2 + 1) * PAD] - 1;   // A-only -> B (set=B, m=1)
                int b2   = (int)vmax[(nn * 2 + 0) * PAD] - 1;   // B-only -> A (set=A, m=0)
                int anyA = (int)vany[nn * PAD];
                float dA = 0.0f;
                if (a2 >= 0) dA = (a2 > 1083) ? 1e9f : sqrtf((float)a2) * 0.05f;
                float dB = 0.0f;
                if (b2 >= 0) dB = anyA ? ((b2 > 1083) ? 1e9f : sqrtf((float)b2) * 0.05f)
                                       : 999.0f;
                sum += fmaxf(dA, dB);
                vmax[(nn * 2 + 0) * PAD] = 0;
                vmax[(nn * 2 + 1) * PAD] = 0;
                vany[nn * PAD] = 0;
            }
            out[0] = sum * 0.5f;
            atomicExch(&g_done, 0);               // restore static-init state for replay
        }
    }
}

extern "C" void kernel_launch(void* const* d_in, const int* in_sizes, int n_in,
                              void* d_out, int out_size)
{
    const float* predict = (const float*)d_in[0];
    const float* targetp = (const float*)d_in[1];
    haus_plane<<<80, 416>>>(predict, targetp, (float*)d_out);
}